// round 10
// baseline (speedup 1.0000x reference)
#include <cuda_runtime.h>
#include <cuda_bf16.h>
#include <cstdint>

typedef unsigned long long ull;

#define M_MODELS 3
#define B_IMG    16
#define N_BOX    512
#define K_TOT    (M_MODELS * N_BOX)   // 1536
#define PAD      2048
#define NUM_CLS  12
#define CAP      256                  // fast-path bucket capacity
#define W_MAX    4                    // CAP/64 mask words per row
#define NMS_THR  512                  // k_nms threads (16 warps)

// ---------------- device scratch (bucket-ordered, written by k_sort) ----------
__device__ float4 g_bbx [B_IMG * K_TOT];   // boxes, bucket order
__device__ float  g_bsc [B_IMG * K_TOT];   // weighted scores, bucket order
__device__ short  g_rank[B_IMG * K_TOT];   // bucket pos -> sorted rank
__device__ int    g_boff[B_IMG * NUM_CLS];
__device__ int    g_bcnt[B_IMG * NUM_CLS];

__device__ __forceinline__ void cswap(ull& x, ull& y, bool up) {
    if ((x > y) == up) { ull t = x; x = y; y = t; }
}

__device__ __forceinline__ ull shfl_stage(ull v, int e, unsigned j, unsigned ks) {
    const ull  o     = __shfl_xor_sync(0xffffffffu, v, j);
    const bool up    = ((e & ks) == 0);
    const bool lower = ((e & j) == 0);
    return ((v < o) == (lower == up)) ? v : o;
}

// division-free exact IoU>0.5 test: 0.5*d is exact in fp32
__device__ __forceinline__ bool iou_gt(const float4 bi, const float ai,
                                       const float4 bj, const float aj) {
    const float iw = fmaxf(fminf(bi.z, bj.z) - fmaxf(bi.x, bj.x), 0.0f);
    const float ih = fmaxf(fminf(bi.w, bj.w) - fmaxf(bi.y, bj.y), 0.0f);
    const float inter = iw * ih;
    const float uni   = ai + aj - inter;
    return inter > 0.5f * fmaxf(uni, 1e-9f);
}

// =============================================================================
// K1: sort (score desc, idx asc) + class compaction + bucket-ordered scatter.
// Bitonic smem stages processed in PAIRS (j, j/2) when j>=128: one thread owns
// a 4-element quad and does both stages in registers -> 9 barriers instead of
// 15. All 4 quad indices share the ks-direction bit (ks >= 4h), so 'up' is
// uniform per quad.
// =============================================================================
__global__ __launch_bounds__(1024)
void k_sort(const float* __restrict__ boxes, const float* __restrict__ scores,
            const int* __restrict__ labels, const float* __restrict__ weights) {
    extern __shared__ char dyn[];
    ull*    key  = (ull*)dyn;                    // 16384 B
    float4* sbox = (float4*)(dyn + PAD * 8);     // 24576 B (sorted boxes)
    __shared__ short slab[K_TOT];
    __shared__ short sidx[K_TOT];                // bucket pos -> rank
    __shared__ int   soff[NUM_CLS], scnt[NUM_CLS];

    const int b    = blockIdx.x;
    const int tid  = threadIdx.x;
    const int warp = tid >> 5, lane = tid & 31;
    const int eA   = (warp << 6) | lane;
    const int eB   = eA | 32;

    const float w0 = weights[0], w1 = weights[1], w2 = weights[2];

    // ---- phase 1: hybrid bitonic sort ----
    auto mkkey = [&](int s) -> ull {
        if (s >= K_TOT) return ~0ull;
        const int m = s >> 9, n = s & (N_BOX - 1);
        const float wm = (m == 0) ? w0 : ((m == 1) ? w1 : w2);
        const float sc = scores[(m * B_IMG + b) * N_BOX + n] * wm;
        return ((ull)(~__float_as_uint(sc)) << 32) | (unsigned)s;
    };
    ull a = mkkey(eA);
    ull c = mkkey(eB);

    #pragma unroll
    for (int kb = 1; kb <= 6; kb++) {
        const unsigned ks = 1u << kb;
        if (ks == 64) cswap(a, c, ((eA & 64) == 0));
        const unsigned jstart = (ks == 64) ? 16u : (ks >> 1);
        #pragma unroll
        for (unsigned j = jstart; j >= 1; j >>= 1) {
            a = shfl_stage(a, eA, j, ks);
            c = shfl_stage(c, eB, j, ks);
        }
    }
    key[eA] = a;
    key[eB] = c;

    #pragma unroll
    for (unsigned ks = 128; ks <= PAD; ks <<= 1) {
        unsigned j = ks >> 1;
        while (j >= 64) {
            if (j >= 128) {
                // paired stages (j, h=j/2), 4 elements per thread, 512 threads
                __syncthreads();
                if (tid < 512) {
                    const unsigned h  = j >> 1;
                    const unsigned bq = ((tid & ~(h - 1)) << 2) | (tid & (h - 1));
                    ull x0 = key[bq];
                    ull x1 = key[bq + h];
                    ull x2 = key[bq + 2 * h];
                    ull x3 = key[bq + 3 * h];
                    const bool up = ((bq & ks) == 0);
                    cswap(x0, x2, up); cswap(x1, x3, up);   // stage j
                    cswap(x0, x1, up); cswap(x2, x3, up);   // stage h
                    key[bq]         = x0;
                    key[bq + h]     = x1;
                    key[bq + 2 * h] = x2;
                    key[bq + 3 * h] = x3;
                }
                j >>= 2;
            } else {
                // single stage j == 64
                __syncthreads();
                const unsigned i = ((tid & ~(j - 1)) << 1) | (tid & (j - 1));
                const unsigned p = i | j;
                const ull x = key[i];
                const ull y = key[p];
                const bool up = ((i & ks) == 0);
                if ((x > y) == up) { key[i] = y; key[p] = x; }
                j >>= 1;
            }
        }
        __syncthreads();
        a = key[eA]; c = key[eB];
        cswap(a, c, ((eA & ks) == 0));                      // j=32
        #pragma unroll
        for (unsigned jr = 16; jr >= 1; jr >>= 1) {
            a = shfl_stage(a, eA, jr, ks);
            c = shfl_stage(c, eB, jr, ks);
        }
        key[eA] = a; key[eB] = c;
    }
    __syncthreads();

    // ---- phase 2: gather sorted boxes + labels into smem ----
    for (int r = tid; r < K_TOT; r += 1024) {
        const int e = (int)(key[r] & 0xffffffffu);
        const int m = e >> 9, n = e & (N_BOX - 1);
        const size_t src = ((size_t)m * B_IMG + b) * N_BOX + n;
        sbox[r] = *(const float4*)&boxes[src * 4];
        slab[r] = (short)labels[src];
    }
    __syncthreads();

    // ---- phase 3: stable per-class compaction (warp l = class l) ----
    if (warp < NUM_CLS) {
        int cnt = 0;
        for (int base = 0; base < K_TOT; base += 32) {
            const bool m = (slab[base + lane] == (short)warp);
            cnt += __popc(__ballot_sync(0xffffffffu, m));
        }
        if (lane == 0) scnt[warp] = cnt;
    }
    __syncthreads();
    if (tid == 0) {
        int acc = 0;
        #pragma unroll
        for (int l = 0; l < NUM_CLS; l++) { soff[l] = acc; acc += scnt[l]; }
    }
    __syncthreads();
    if (warp < NUM_CLS) {
        const int off = soff[warp];
        int cnt = 0;
        for (int base = 0; base < K_TOT; base += 32) {
            const bool m = (slab[base + lane] == (short)warp);
            const unsigned bal = __ballot_sync(0xffffffffu, m);
            if (m) {
                const int pos = cnt + __popc(bal & ((1u << lane) - 1u));
                sidx[off + pos] = (short)(base + lane);
            }
            cnt += __popc(bal);
        }
        if (lane == 0) {
            g_boff[b * NUM_CLS + warp] = off;
            g_bcnt[b * NUM_CLS + warp] = cnt;
        }
    }
    __syncthreads();

    // ---- phase 4: bucket-ordered scatter to global (coalesced writes) ----
    for (int e = tid; e < K_TOT; e += 1024) {
        const int rank = sidx[e];
        const size_t dst = (size_t)b * K_TOT + e;
        g_bbx [dst] = sbox[rank];
        g_bsc [dst] = __uint_as_float(~(unsigned)(key[rank] >> 32));
        g_rank[dst] = (short)rank;
    }
}

// =============================================================================
// K2: per-(image,class) NMS, 512 threads. Coalesced bucket load (boxes, score,
// rank all prefetched to SMEM) -> 16-warp matrix build with rowNZ tracking ->
// single-thread register-resident sparse greedy chase -> output (no global
// loads after the chase).
// =============================================================================
__global__ __launch_bounds__(NMS_THR)
void k_nms(float* __restrict__ out) {
    __shared__ float4 bx[CAP];
    __shared__ float  ar[CAP];
    __shared__ float  sc[CAP];
    __shared__ short  rk[CAP];
    __shared__ ull    smask[CAP * W_MAX];     // 8 KB
    __shared__ ull    rownz[W_MAX];
    __shared__ ull    keepw[W_MAX];

    const int img  = blockIdx.x / NUM_CLS;
    const int cls  = blockIdx.x % NUM_CLS;
    const int tid  = threadIdx.x;
    const int warp = tid >> 5, lane = tid & 31;

    const int off = g_boff[img * NUM_CLS + cls];
    const int cnt = g_bcnt[img * NUM_CLS + cls];
    if (cnt == 0) return;

    const size_t gbase = (size_t)img * K_TOT + off;

    if (cnt <= CAP) {
        if (tid < W_MAX) { rownz[tid] = 0ull; keepw[tid] = ~0ull; }
        for (int m = tid; m < cnt; m += NMS_THR) {
            const float4 bb = g_bbx[gbase + m];
            bx[m] = bb;
            ar[m] = (bb.z - bb.x) * (bb.w - bb.y);
            sc[m] = g_bsc [gbase + m];
            rk[m] = g_rank[gbase + m];
        }
        __syncthreads();

        const int W = (cnt + 63) >> 6;
        // ---- matrix build: rows striped over 16 warps ----
        for (int r = warp; r < cnt; r += 16) {
            const float4 bi = bx[r];
            const float  ai = ar[r];
            ull nz = 0ull;
            for (int w = r >> 6; w < W; w++) {
                const int j0 = w * 64 + lane;
                const int j1 = j0 + 32;
                bool p0 = false, p1 = false;
                if (j0 > r && j0 < cnt) p0 = iou_gt(bi, ai, bx[j0], ar[j0]);
                if (j1 > r && j1 < cnt) p1 = iou_gt(bi, ai, bx[j1], ar[j1]);
                const unsigned lo = __ballot_sync(0xffffffffu, p0);
                const unsigned hi = __ballot_sync(0xffffffffu, p1);
                const ull mword = ((ull)hi << 32) | lo;
                if (lane == 0) smask[r * W_MAX + w] = mword;
                nz |= mword;
            }
            if (lane == 0 && nz)
                atomicOr(&rownz[r >> 6], 1ull << (r & 63));
        }
        __syncthreads();

        // ---- sparse greedy chase, single thread, removed[] in registers ----
        if (tid == 0) {
            ull rem0 = 0, rem1 = 0, rem2 = 0, rem3 = 0;
            #pragma unroll
            for (int w = 0; w < W_MAX; w++) {
                if (w >= W) break;
                ull act = rownz[w];
                ull rw  = (w == 0) ? rem0 : (w == 1) ? rem1 : (w == 2) ? rem2 : rem3;
                act &= ~rw;
                while (act) {
                    const int bit = __ffsll((long long)act) - 1;
                    act &= act - 1;
                    if (!((rw >> bit) & 1ull)) {
                        const int i = w * 64 + bit;
                        const ull* row = &smask[i * W_MAX];
                        if (w <= 0) rem0 |= row[0];
                        if (w <= 1 && W > 1) rem1 |= row[1];
                        if (w <= 2 && W > 2) rem2 |= row[2];
                        if (w <= 3 && W > 3) rem3 |= row[3];
                        rw = (w == 0) ? rem0 : (w == 1) ? rem1 : (w == 2) ? rem2 : rem3;
                        act &= ~rw;
                    }
                }
            }
            keepw[0] = ~rem0; keepw[1] = ~rem1; keepw[2] = ~rem2; keepw[3] = ~rem3;
        }
        __syncthreads();

        // ---- output this bucket's rows (SMEM only) ----
        for (int m = tid; m < cnt; m += NMS_THR) {
            const bool kp = (keepw[m >> 6] >> (m & 63)) & 1ull;
            const float f = kp ? 1.0f : 0.0f;
            const float4 bb = bx[m];
            const size_t o = ((size_t)img * K_TOT + rk[m]) * 5;
            out[o + 0] = bb.x * f;
            out[o + 1] = bb.y * f;
            out[o + 2] = bb.z * f;
            out[o + 3] = bb.w * f;
            out[o + 4] = sc[m] * f;
        }
    } else {
        // ---- fallback (cnt > CAP): warp-serial kept-list from global ----
        __shared__ short kidx[K_TOT];
        if (warp == 0) {
            int nk = 0;
            for (int cix = 0; cix < cnt; cix++) {
                const float4 bc = g_bbx[gbase + cix];
                const float  ac = (bc.z - bc.x) * (bc.w - bc.y);
                bool sup = false;
                for (int k = lane; k < nk; k += 32) {
                    const float4 bk = g_bbx[gbase + kidx[k]];
                    const float  ak = (bk.z - bk.x) * (bk.w - bk.y);
                    if (iou_gt(bc, ac, bk, ak)) { sup = true; break; }
                }
                sup = (__ballot_sync(0xffffffffu, sup) != 0u);
                if (!sup) {
                    if (lane == 0) kidx[nk] = (short)cix;
                    nk++;
                }
                if (lane == 0) {
                    const float f = sup ? 0.0f : 1.0f;
                    const int rank = g_rank[gbase + cix];
                    const size_t o = ((size_t)img * K_TOT + rank) * 5;
                    out[o + 0] = bc.x * f;
                    out[o + 1] = bc.y * f;
                    out[o + 2] = bc.z * f;
                    out[o + 3] = bc.w * f;
                    out[o + 4] = g_bsc[gbase + cix] * f;
                }
                __syncwarp();
            }
        }
    }
}

// =============================================================================
extern "C" void kernel_launch(void* const* d_in, const int* in_sizes, int n_in,
                              void* d_out, int out_size) {
    const float* boxes   = (const float*)d_in[0];
    const float* scores  = (const float*)d_in[1];
    const int*   labels  = (const int*)  d_in[2];
    const float* weights = (const float*)d_in[3];
    float*       out     = (float*)d_out;

    k_sort<<<B_IMG, 1024, PAD * 8 + K_TOT * 16>>>(boxes, scores, labels, weights);
    k_nms <<<B_IMG * NUM_CLS, NMS_THR>>>(out);
}

// round 11
// speedup vs baseline: 1.1057x; 1.1057x over previous
#include <cuda_runtime.h>
#include <cuda_bf16.h>
#include <cstdint>

typedef unsigned long long ull;

#define M_MODELS 3
#define B_IMG    16
#define N_BOX    512
#define K_TOT    (M_MODELS * N_BOX)   // 1536
#define PAD      2048
#define NUM_CLS  12
#define CAP      256                  // fast-path bucket capacity
#define W_MAX    4                    // CAP/64 mask words per row
#define NMS_THR  512                  // k_nms threads (16 warps)

// ---------------- device scratch (bucket-ordered, written by k_sort) ----------
__device__ float4 g_bbx [B_IMG * K_TOT];   // boxes, bucket order
__device__ float4 g_aux [B_IMG * K_TOT];   // (score, area, rank, 0), bucket order
__device__ int    g_boff[B_IMG * NUM_CLS];
__device__ int    g_bcnt[B_IMG * NUM_CLS];

__device__ __forceinline__ void cswap(ull& x, ull& y, bool up) {
    if ((x > y) == up) { ull t = x; x = y; y = t; }
}

__device__ __forceinline__ ull shfl_stage(ull v, int e, unsigned j, unsigned ks) {
    const ull  o     = __shfl_xor_sync(0xffffffffu, v, j);
    const bool up    = ((e & ks) == 0);
    const bool lower = ((e & j) == 0);
    return ((v < o) == (lower == up)) ? v : o;
}

// division-free exact IoU>0.5 test: 0.5*d is exact in fp32
__device__ __forceinline__ bool iou_gt(const float4 bi, const float ai,
                                       const float4 bj, const float aj) {
    const float iw = fmaxf(fminf(bi.z, bj.z) - fmaxf(bi.x, bj.x), 0.0f);
    const float ih = fmaxf(fminf(bi.w, bj.w) - fmaxf(bi.y, bj.y), 0.0f);
    const float inter = iw * ih;
    const float uni   = ai + aj - inter;
    return inter > 0.5f * fmaxf(uni, 1e-9f);
}

__device__ __forceinline__ void pdl_launch_dependents() {
    asm volatile("griddepcontrol.launch_dependents;");
}
__device__ __forceinline__ void pdl_wait() {
    asm volatile("griddepcontrol.wait;" ::: "memory");
}

// =============================================================================
// K1: sort (score desc, idx asc) + class compaction + bucket-ordered scatter.
// (R9 stage structure — all 1024 threads active every smem stage.)
// =============================================================================
__global__ __launch_bounds__(1024)
void k_sort(const float* __restrict__ boxes, const float* __restrict__ scores,
            const int* __restrict__ labels, const float* __restrict__ weights) {
    extern __shared__ char dyn[];
    ull*    key  = (ull*)dyn;                    // 16384 B
    float4* sbox = (float4*)(dyn + PAD * 8);     // 24576 B (sorted boxes)
    __shared__ short slab[K_TOT];
    __shared__ short sidx[K_TOT];                // bucket pos -> rank
    __shared__ int   soff[NUM_CLS], scnt[NUM_CLS];

    pdl_launch_dependents();   // let k_nms blocks stage early; they wait on data

    const int b    = blockIdx.x;
    const int tid  = threadIdx.x;
    const int warp = tid >> 5, lane = tid & 31;
    const int eA   = (warp << 6) | lane;
    const int eB   = eA | 32;

    const float w0 = weights[0], w1 = weights[1], w2 = weights[2];

    // ---- phase 1: hybrid bitonic sort ----
    auto mkkey = [&](int s) -> ull {
        if (s >= K_TOT) return ~0ull;
        const int m = s >> 9, n = s & (N_BOX - 1);
        const float wm = (m == 0) ? w0 : ((m == 1) ? w1 : w2);
        const float sc = scores[(m * B_IMG + b) * N_BOX + n] * wm;
        return ((ull)(~__float_as_uint(sc)) << 32) | (unsigned)s;
    };
    ull a = mkkey(eA);
    ull c = mkkey(eB);

    #pragma unroll
    for (int kb = 1; kb <= 6; kb++) {
        const unsigned ks = 1u << kb;
        if (ks == 64) cswap(a, c, ((eA & 64) == 0));
        const unsigned jstart = (ks == 64) ? 16u : (ks >> 1);
        #pragma unroll
        for (unsigned j = jstart; j >= 1; j >>= 1) {
            a = shfl_stage(a, eA, j, ks);
            c = shfl_stage(c, eB, j, ks);
        }
    }
    key[eA] = a;
    key[eB] = c;

    #pragma unroll
    for (unsigned ks = 128; ks <= PAD; ks <<= 1) {
        for (unsigned j = ks >> 1; j >= 64; j >>= 1) {
            __syncthreads();
            const unsigned i = ((tid & ~(j - 1)) << 1) | (tid & (j - 1));
            const unsigned p = i | j;
            const ull x = key[i];
            const ull y = key[p];
            const bool up = ((i & ks) == 0);
            if ((x > y) == up) { key[i] = y; key[p] = x; }
        }
        __syncthreads();
        a = key[eA]; c = key[eB];
        cswap(a, c, ((eA & ks) == 0));
        #pragma unroll
        for (unsigned jr = 16; jr >= 1; jr >>= 1) {
            a = shfl_stage(a, eA, jr, ks);
            c = shfl_stage(c, eB, jr, ks);
        }
        key[eA] = a; key[eB] = c;
    }
    __syncthreads();

    // ---- phase 2: gather sorted boxes + labels into smem ----
    for (int r = tid; r < K_TOT; r += 1024) {
        const int e = (int)(key[r] & 0xffffffffu);
        const int m = e >> 9, n = e & (N_BOX - 1);
        const size_t src = ((size_t)m * B_IMG + b) * N_BOX + n;
        sbox[r] = *(const float4*)&boxes[src * 4];
        slab[r] = (short)labels[src];
    }
    __syncthreads();

    // ---- phase 3: stable per-class compaction (warp l = class l) ----
    if (warp < NUM_CLS) {
        int cnt = 0;
        for (int base = 0; base < K_TOT; base += 32) {
            const bool m = (slab[base + lane] == (short)warp);
            cnt += __popc(__ballot_sync(0xffffffffu, m));
        }
        if (lane == 0) scnt[warp] = cnt;
    }
    __syncthreads();
    if (tid == 0) {
        int acc = 0;
        #pragma unroll
        for (int l = 0; l < NUM_CLS; l++) { soff[l] = acc; acc += scnt[l]; }
    }
    __syncthreads();
    if (warp < NUM_CLS) {
        const int off = soff[warp];
        int cnt = 0;
        for (int base = 0; base < K_TOT; base += 32) {
            const bool m = (slab[base + lane] == (short)warp);
            const unsigned bal = __ballot_sync(0xffffffffu, m);
            if (m) {
                const int pos = cnt + __popc(bal & ((1u << lane) - 1u));
                sidx[off + pos] = (short)(base + lane);
            }
            cnt += __popc(bal);
        }
        if (lane == 0) {
            g_boff[b * NUM_CLS + warp] = off;
            g_bcnt[b * NUM_CLS + warp] = cnt;
        }
    }
    __syncthreads();

    // ---- phase 4: bucket-ordered scatter to global (coalesced writes) ----
    for (int e = tid; e < K_TOT; e += 1024) {
        const int rank = sidx[e];
        const size_t dst = (size_t)b * K_TOT + e;
        const float4 bb = sbox[rank];
        g_bbx[dst] = bb;
        g_aux[dst] = make_float4(__uint_as_float(~(unsigned)(key[rank] >> 32)),
                                 (bb.z - bb.x) * (bb.w - bb.y),
                                 (float)rank, 0.0f);
    }
}

// =============================================================================
// K2: per-(image,class) NMS, 512 threads, launched with PDL so blocks are
// resident before k_sort retires. Coalesced bucket load -> 16-warp matrix
// build with rowNZ tracking -> single-thread register-resident sparse greedy
// chase -> output (no global loads after the chase).
// =============================================================================
__global__ __launch_bounds__(NMS_THR)
void k_nms(float* __restrict__ out) {
    __shared__ float4 bx[CAP];
    __shared__ float  ar[CAP];
    __shared__ float  sc[CAP];
    __shared__ short  rk[CAP];
    __shared__ ull    smask[CAP * W_MAX];     // 8 KB
    __shared__ ull    rownz[W_MAX];
    __shared__ ull    keepw[W_MAX];

    const int img  = blockIdx.x / NUM_CLS;
    const int cls  = blockIdx.x % NUM_CLS;
    const int tid  = threadIdx.x;
    const int warp = tid >> 5, lane = tid & 31;

    if (tid < W_MAX) { rownz[tid] = 0ull; keepw[tid] = ~0ull; }

    pdl_wait();   // k_sort's writes are visible from here

    const int off = g_boff[img * NUM_CLS + cls];
    const int cnt = g_bcnt[img * NUM_CLS + cls];
    if (cnt == 0) return;

    const size_t gbase = (size_t)img * K_TOT + off;

    if (cnt <= CAP) {
        for (int m = tid; m < cnt; m += NMS_THR) {
            const float4 bb = g_bbx[gbase + m];
            const float4 ax = g_aux[gbase + m];
            bx[m] = bb;
            ar[m] = ax.y;
            sc[m] = ax.x;
            rk[m] = (short)ax.z;
        }
        __syncthreads();

        const int W = (cnt + 63) >> 6;
        // ---- matrix build: rows striped over 16 warps ----
        for (int r = warp; r < cnt; r += 16) {
            const float4 bi = bx[r];
            const float  ai = ar[r];
            ull nz = 0ull;
            for (int w = r >> 6; w < W; w++) {
                const int j0 = w * 64 + lane;
                const int j1 = j0 + 32;
                bool p0 = false, p1 = false;
                if (j0 > r && j0 < cnt) p0 = iou_gt(bi, ai, bx[j0], ar[j0]);
                if (j1 > r && j1 < cnt) p1 = iou_gt(bi, ai, bx[j1], ar[j1]);
                const unsigned lo = __ballot_sync(0xffffffffu, p0);
                const unsigned hi = __ballot_sync(0xffffffffu, p1);
                const ull mword = ((ull)hi << 32) | lo;
                if (lane == 0) smask[r * W_MAX + w] = mword;
                nz |= mword;
            }
            if (lane == 0 && nz)
                atomicOr(&rownz[r >> 6], 1ull << (r & 63));
        }
        __syncthreads();

        // ---- sparse greedy chase, single thread, removed[] in registers ----
        if (tid == 0) {
            ull rem0 = 0, rem1 = 0, rem2 = 0, rem3 = 0;
            #pragma unroll
            for (int w = 0; w < W_MAX; w++) {
                if (w >= W) break;
                ull act = rownz[w];
                ull rw  = (w == 0) ? rem0 : (w == 1) ? rem1 : (w == 2) ? rem2 : rem3;
                act &= ~rw;
                while (act) {
                    const int bit = __ffsll((long long)act) - 1;
                    act &= act - 1;
                    if (!((rw >> bit) & 1ull)) {
                        const int i = w * 64 + bit;
                        const ull* row = &smask[i * W_MAX];
                        if (w <= 0) rem0 |= row[0];
                        if (w <= 1 && W > 1) rem1 |= row[1];
                        if (w <= 2 && W > 2) rem2 |= row[2];
                        if (w <= 3 && W > 3) rem3 |= row[3];
                        rw = (w == 0) ? rem0 : (w == 1) ? rem1 : (w == 2) ? rem2 : rem3;
                        act &= ~rw;
                    }
                }
            }
            keepw[0] = ~rem0; keepw[1] = ~rem1; keepw[2] = ~rem2; keepw[3] = ~rem3;
        }
        __syncthreads();

        // ---- output this bucket's rows (SMEM only) ----
        for (int m = tid; m < cnt; m += NMS_THR) {
            const bool kp = (keepw[m >> 6] >> (m & 63)) & 1ull;
            const float f = kp ? 1.0f : 0.0f;
            const float4 bb = bx[m];
            const size_t o = ((size_t)img * K_TOT + rk[m]) * 5;
            out[o + 0] = bb.x * f;
            out[o + 1] = bb.y * f;
            out[o + 2] = bb.z * f;
            out[o + 3] = bb.w * f;
            out[o + 4] = sc[m] * f;
        }
    } else {
        // ---- fallback (cnt > CAP): warp-serial kept-list from global ----
        __shared__ short kidx[K_TOT];
        if (warp == 0) {
            int nk = 0;
            for (int cix = 0; cix < cnt; cix++) {
                const float4 bc = g_bbx[gbase + cix];
                const float  ac = (bc.z - bc.x) * (bc.w - bc.y);
                bool sup = false;
                for (int k = lane; k < nk; k += 32) {
                    const float4 bk = g_bbx[gbase + kidx[k]];
                    const float  ak = (bk.z - bk.x) * (bk.w - bk.y);
                    if (iou_gt(bc, ac, bk, ak)) { sup = true; break; }
                }
                sup = (__ballot_sync(0xffffffffu, sup) != 0u);
                if (!sup) {
                    if (lane == 0) kidx[nk] = (short)cix;
                    nk++;
                }
                if (lane == 0) {
                    const float4 ax = g_aux[gbase + cix];
                    const float f = sup ? 0.0f : 1.0f;
                    const size_t o = ((size_t)img * K_TOT + (int)ax.z) * 5;
                    out[o + 0] = bc.x * f;
                    out[o + 1] = bc.y * f;
                    out[o + 2] = bc.z * f;
                    out[o + 3] = bc.w * f;
                    out[o + 4] = ax.x * f;
                }
                __syncwarp();
            }
        }
    }
}

// =============================================================================
extern "C" void kernel_launch(void* const* d_in, const int* in_sizes, int n_in,
                              void* d_out, int out_size) {
    const float* boxes   = (const float*)d_in[0];
    const float* scores  = (const float*)d_in[1];
    const int*   labels  = (const int*)  d_in[2];
    const float* weights = (const float*)d_in[3];
    float*       out     = (float*)d_out;

    k_sort<<<B_IMG, 1024, PAD * 8 + K_TOT * 16>>>(boxes, scores, labels, weights);

    // PDL launch of k_nms: blocks stage while k_sort drains; device-side
    // griddepcontrol.wait provides the data dependency.
    cudaLaunchConfig_t cfg = {};
    cfg.gridDim  = dim3(B_IMG * NUM_CLS);
    cfg.blockDim = dim3(NMS_THR);
    cfg.dynamicSmemBytes = 0;
    cfg.stream = 0;
    cudaLaunchAttribute attr[1];
    attr[0].id = cudaLaunchAttributeProgrammaticStreamSerialization;
    attr[0].val.programmaticStreamSerializationAllowed = 1;
    cfg.attrs = attr;
    cfg.numAttrs = 1;
    cudaLaunchKernelEx(&cfg, k_nms, out);
}